// round 17
// baseline (speedup 1.0000x reference)
#include <cuda_runtime.h>
#include <cuda_fp16.h>
#include <mma.h>
#include <math.h>

using namespace nvcuda;

#define NS 716
#define DD 64
#define NSAMP 48
#define NTILE 45            // ceil(716/16)
#define FINF 3.402823466e38f
#define LOG2E 1.4426950408889634f

// ---- scratch (device globals; no allocation) ----
__device__ float g_emb[NS * DD];
__device__ __half g_whh[NSAMP * 720 * 64];        // fp16 Wh [s][j][c], rows 716..719 zero
__device__ float g_Wh1[NSAMP * NS];               // pre-scaled by log2e
__device__ float g_Wh2[NSAMP * NS];               // pre-scaled by log2e
__device__ __half g_qh[NSAMP * 720 * 64];         // fp16 q
__device__ __half g_kh[NSAMP * 4 * 720 * 16];     // fp16 [s][h][j][c], rows 716..719 zero
__device__ __half g_vh[NSAMP * 4 * 720 * 16];
__device__ __half g_W16[4 * 64 * 64];             // fp16 W, Wq, Wk, Wv
__device__ float g_cat[NSAMP * NS * 2 * DD];
__device__ unsigned g_cmask[NTILE * NS];
__device__ float g_wa1[DD];
__device__ float g_wa2[DD];
__device__ float g_Wc[DD * DD];   // Wo @ Wp[64:,:]
__device__ float g_bc[DD];        // bo @ Wp[64:,:] + bp

// ---- helpers ----
__device__ __forceinline__ float ex2f(float x) {
    float y;
    asm("ex2.approx.ftz.f32 %0, %1;" : "=f"(y) : "f"(x));
    return y;
}
__device__ __forceinline__ unsigned long long pack2(float lo, float hi) {
    unsigned long long r;
    asm("mov.b64 %0, {%1, %2};" : "=l"(r) : "f"(lo), "f"(hi));
    return r;
}
__device__ __forceinline__ void unpack2(unsigned long long v, float& lo, float& hi) {
    asm("mov.b64 {%0, %1}, %2;" : "=f"(lo), "=f"(hi) : "l"(v));
}
__device__ __forceinline__ unsigned long long ffma2(unsigned long long a,
                                                    unsigned long long b,
                                                    unsigned long long c) {
    unsigned long long d;
    asm("fma.rn.f32x2 %0, %1, %2, %3;" : "=l"(d) : "l"(a), "l"(b), "l"(c));
    return d;
}
__device__ __forceinline__ void cp_async16(unsigned sa, const void* g) {
    asm volatile("cp.async.cg.shared.global [%0], [%1], 16;" :: "r"(sa), "l"(g));
}

// ============================================================
// Kernel PRE: adjacency pack + embedding gather + weight prep (incl fp16 W)
// grid 181 x 256
// ============================================================
__global__ void pre_kernel(const int* __restrict__ adj,
                           const float* __restrict__ in_emb,
                           const float* __restrict__ out_emb,
                           const int* __restrict__ ind,
                           const int* __restrict__ outd,
                           const float* __restrict__ W,
                           const float* __restrict__ a1, const float* __restrict__ a2,
                           const float* __restrict__ Wq, const float* __restrict__ Wk,
                           const float* __restrict__ Wv,
                           const float* __restrict__ Wo, const float* __restrict__ bo,
                           const float* __restrict__ Wp, const float* __restrict__ bp) {
    int b = blockIdx.x, tid = threadIdx.x;
    if (b < 135) {
        int t = b / 3;
        int j = (b % 3) * 256 + tid;
        if (j < NS) {
            unsigned w = 0;
            #pragma unroll
            for (int ti = 0; ti < 16; ti++) {
                int i = t * 16 + ti;
                if (i < NS && adj[i * NS + j] != 0) w |= (1u << ti);
            }
            g_cmask[t * NS + j] = w;
        }
    } else if (b < 180) {
        int idx = (b - 135) * 256 + tid;
        if (idx < NS * 16) {
            int n = idx >> 4;
            int c4 = (idx & 15) * 4;
            float4 a = *(const float4*)&in_emb[ind[n] * DD + c4];
            float4 bb = *(const float4*)&out_emb[outd[n] * DD + c4];
            float4 r = {a.x + bb.x, a.y + bb.y, a.z + bb.z, a.w + bb.w};
            *(float4*)&g_emb[n * DD + c4] = r;
        }
    } else {
        if (tid < DD) {
            float s1 = 0.f, s2 = 0.f;
            #pragma unroll 8
            for (int c = 0; c < DD; c++) {
                float w = W[tid * DD + c];
                s1 = fmaf(w, a1[c], s1);
                s2 = fmaf(w, a2[c], s2);
            }
            g_wa1[tid] = s1 * LOG2E; g_wa2[tid] = s2 * LOG2E;
            float bsum = bp[tid];
            #pragma unroll 8
            for (int m = 0; m < DD; m++) bsum = fmaf(bo[m], Wp[(DD + m) * DD + tid], bsum);
            g_bc[tid] = bsum;
        }
        for (int o = tid; o < DD * DD; o += 256) {
            int k = o >> 6, c = o & 63;
            float acc = 0.f;
            #pragma unroll 8
            for (int m = 0; m < DD; m++)
                acc = fmaf(Wo[k * DD + m], Wp[(DD + m) * DD + c], acc);
            g_Wc[o] = acc;
        }
        // fp16 copies of the 4 projection matrices
        for (int o = tid; o < 4096; o += 256) {
            g_W16[o]           = __float2half(W[o]);
            g_W16[4096 + o]    = __float2half(Wq[o]);
            g_W16[8192 + o]    = __float2half(Wk[o]);
            g_W16[12288 + o]   = __float2half(Wv[o]);
        }
    }
}

// ============================================================
// Kernel B: TC projections + Wh1/Wh2 (fp32 path). grid (48, 23), block 256.
// ============================================================
#define BROWS 32
__global__ __launch_bounds__(256) void proj_kernel(
    const float* __restrict__ x,
    const float* __restrict__ bq, const float* __restrict__ bk,
    const float* __restrict__ bv) {
    __shared__ float xs[BROWS][DD];
    __shared__ float ys[BROWS][DD];
    __shared__ __half xh[BROWS][DD];
    __shared__ __half yh[BROWS][DD];
    __shared__ float bpl[4][16][DD];
    int s = blockIdx.x;
    int n0 = blockIdx.y * BROWS;
    int tid = threadIdx.x, lane = tid & 31, w = tid >> 5;

    #pragma unroll
    for (int half = 0; half < 2; half++) {
        int idx = half * 256 + tid;
        int r = idx >> 4, k4 = (idx & 15) * 4;
        int nn = min(n0 + r, NS - 1);
        float4 xv = *(const float4*)&x[(size_t)(s * NS + nn) * DD + k4];
        float4 ev = *(const float4*)&g_emb[nn * DD + k4];
        *(float4*)&xs[r][k4] = xv;
        float4 yv = {xv.x + ev.x, xv.y + ev.y, xv.z + ev.z, xv.w + ev.w};
        *(float4*)&ys[r][k4] = yv;
    }
    // bias planes (row-replicated)
    for (int idx = tid; idx < 4096; idx += 256) {
        int m = idx >> 10, c = idx & 63;
        float v = (m == 1) ? bq[c] : (m == 2) ? bk[c] : (m == 3) ? bv[c] : 0.f;
        bpl[m][(idx >> 6) & 15][c] = v;
    }
    __syncthreads();

    // Wh1/Wh2 (fp32, log2e-scaled)
    {
        float wa10 = g_wa1[lane], wa11 = g_wa1[32 + lane];
        float wa20 = g_wa2[lane], wa21 = g_wa2[32 + lane];
        #pragma unroll
        for (int rr = 0; rr < 4; rr++) {
            int r = w * 4 + rr, n = n0 + r;
            float x0 = xs[r][lane], x1 = xs[r][32 + lane];
            float s1 = x0 * wa10 + x1 * wa11;
            float s2 = x0 * wa20 + x1 * wa21;
            #pragma unroll
            for (int off = 16; off; off >>= 1) {
                s1 += __shfl_xor_sync(0xffffffffu, s1, off);
                s2 += __shfl_xor_sync(0xffffffffu, s2, off);
            }
            if (lane == 0 && n < NS) {
                g_Wh1[s * NS + n] = s1;
                g_Wh2[s * NS + n] = s2;
            }
        }
    }

    // fp16 staging (zero rows beyond NS so pad rows of outputs vanish)
    #pragma unroll
    for (int e = 0; e < 4; e++) {
        int idx = e * 256 + tid;           // half2 index, 0..1023
        int r = idx >> 5, cp = idx & 31;
        bool in = (n0 + r) < NS;
        float a = in ? xs[r][cp * 2] : 0.f;
        float b = in ? xs[r][cp * 2 + 1] : 0.f;
        *(__half2*)&xh[r][cp * 2] = __floats2half2_rn(a, b);
        float a2 = in ? ys[r][cp * 2] : 0.f;
        float b2 = in ? ys[r][cp * 2 + 1] : 0.f;
        *(__half2*)&yh[r][cp * 2] = __floats2half2_rn(a2, b2);
    }
    __syncthreads();

    // 32 output tiles: tix = m*8 + rt*4 + ct; warp w does tix = w + 8i
    #pragma unroll
    for (int i = 0; i < 4; i++) {
        int tix = w + i * 8;
        int m = tix >> 3, rt = (tix >> 2) & 1, ct = tix & 3;
        wmma::fragment<wmma::accumulator, 16, 16, 16, float> acc;
        wmma::load_matrix_sync(acc, &bpl[m][0][0] + ct * 16, 64, wmma::mem_row_major);
        const __half* asrc = (m == 0 ? &xh[0][0] : &yh[0][0]) + rt * 16 * 64;
        const __half* bsrc = g_W16 + m * 4096 + ct * 16;
        #pragma unroll
        for (int ks = 0; ks < 4; ks++) {
            wmma::fragment<wmma::matrix_a, 16, 16, 16, __half, wmma::row_major> af;
            wmma::load_matrix_sync(af, asrc + ks * 16, 64);
            wmma::fragment<wmma::matrix_b, 16, 16, 16, __half, wmma::row_major> bf;
            wmma::load_matrix_sync(bf, bsrc + ks * 16 * 64, 64);
            wmma::mma_sync(acc, af, bf, acc);
        }
        wmma::fragment<wmma::accumulator, 16, 16, 16, __half> hf;
        #pragma unroll
        for (int e = 0; e < acc.num_elements; e++) hf.x[e] = __float2half(acc.x[e]);
        int rowbase = n0 + rt * 16;
        if (rowbase < 720) {
            if (m == 0)
                wmma::store_matrix_sync(&g_whh[(size_t)(s * 720 + rowbase) * 64 + ct * 16],
                                        hf, 64, wmma::mem_row_major);
            else if (m == 1)
                wmma::store_matrix_sync(&g_qh[(size_t)(s * 720 + rowbase) * 64 + ct * 16],
                                        hf, 64, wmma::mem_row_major);
            else if (m == 2)
                wmma::store_matrix_sync(&g_kh[(size_t)((s * 4 + ct) * 720 + rowbase) * 16],
                                        hf, 16, wmma::mem_row_major);
            else
                wmma::store_matrix_sync(&g_vh[(size_t)((s * 4 + ct) * 720 + rowbase) * 16],
                                        hf, 16, wmma::mem_row_major);
        }
    }

    // last block: re-zero pad rows 716..719 (bias could make them nonzero)
    if (blockIdx.y == 22) {
        __syncthreads();
        for (int o = tid; o < 256; o += 256) {   // whh: 4 rows x 64
            int r = 716 + (o >> 6), c = o & 63;
            g_whh[(size_t)(s * 720 + r) * 64 + c] = __half(0);
        }
        for (int o = tid; o < 256; o += 256) {   // kh/vh: 4 heads x 4 rows x 16
            int hh = o >> 6, r = 716 + ((o >> 4) & 3), c = o & 15;
            g_kh[(size_t)((s * 4 + hh) * 720 + r) * 16 + c] = __half(0);
            g_vh[(size_t)((s * 4 + hh) * 720 + r) * 16 + c] = __half(0);
        }
    }
}

// ============================================================
// Kernel D: GAT, TC PV + mma rowsum + separable exp2 (2 MUFU per j).
// grid (48,45), block 256 (8 warps = 4 n-tiles x 2 j-halves).
// ============================================================
__global__ __launch_bounds__(256) void gat_kernel() {
    __shared__ __align__(32) __half ph[16 * 720];   // overlaid by o/l after PV

    int s = blockIdx.x, t = blockIdx.y;
    int i0 = t * 16;
    int tid = threadIdx.x, w = tid >> 5;
    const unsigned* __restrict__ cm = g_cmask + t * NS;
    const float* __restrict__ wh2 = g_Wh2 + s * NS;

    float e1p[16], e1n[16], thr[16];
    #pragma unroll
    for (int ti = 0; ti < 16; ti++) {
        int i = min(i0 + ti, NS - 1);
        float v = g_Wh1[s * NS + i];
        e1p[ti] = ex2f(v);
        e1n[ti] = ex2f(0.2f * v);
        thr[ti] = -v;
    }

    // exp2(lrelu(a+b)) = (b > -a) ? 2^a 2^b : 2^{.2a} 2^{.2b}
    for (int j = tid; j < 720; j += 256) {
        bool in = j < NS;
        float w2 = in ? wh2[j] : 0.f;
        unsigned mk = in ? cm[j] : 0u;
        float e2p = ex2f(w2), e2n = ex2f(0.2f * w2);
        #pragma unroll
        for (int ti = 0; ti < 16; ti++) {
            float pe = (w2 > thr[ti]) ? e1p[ti] * e2p : e1n[ti] * e2n;
            pe = ((mk >> ti) & 1u) ? pe : 0.0f;
            ph[ti * 720 + j] = __float2half(pe);
        }
    }
    __syncthreads();

    int nt = w & 3, jh = w >> 2;
    wmma::fragment<wmma::accumulator, 16, 16, 16, float> ofrag, lfrag;
    wmma::fill_fragment(ofrag, 0.0f);
    wmma::fill_fragment(lfrag, 0.0f);
    wmma::fragment<wmma::matrix_b, 16, 16, 16, __half, wmma::row_major> bones;
    wmma::fill_fragment(bones, __float2half(1.0f));

    const __half* whh = g_whh + (size_t)s * 720 * 64;
    int c0 = jh ? 23 : 0, c1 = jh ? 45 : 23;
    for (int ch = c0; ch < c1; ch++) {
        wmma::fragment<wmma::matrix_a, 16, 16, 16, __half, wmma::row_major> pa;
        wmma::load_matrix_sync(pa, ph + ch * 16, 720);
        wmma::fragment<wmma::matrix_b, 16, 16, 16, __half, wmma::row_major> vb;
        wmma::load_matrix_sync(vb, whh + (size_t)ch * 16 * 64 + nt * 16, 64);
        wmma::mma_sync(ofrag, pa, vb, ofrag);
        if (nt == 0) wmma::mma_sync(lfrag, pa, bones, lfrag);
    }
    __syncthreads();

    float* osm = (float*)ph;            // [8][256]
    float* lsm = osm + 2048;            // [2][256]
    wmma::store_matrix_sync(osm + w * 256, ofrag, 16, wmma::mem_row_major);
    if (nt == 0) wmma::store_matrix_sync(lsm + jh * 256, lfrag, 16, wmma::mem_row_major);
    __syncthreads();

    #pragma unroll
    for (int e = 0; e < 4; e++) {
        int idx = e * 256 + tid;
        int r = idx >> 6, c = idx & 63;
        int nt2 = c >> 4, cc = c & 15;
        float o = osm[nt2 * 256 + r * 16 + cc] + osm[(4 + nt2) * 256 + r * 16 + cc];
        float l = lsm[r * 16] + lsm[256 + r * 16];
        float v = o / l;
        v = v > 0.f ? v : expm1f(v);
        int i = i0 + r;
        if (i < NS)
            g_cat[(size_t)(s * NS + i) * 2 * DD + c] = v;
    }
}

// ============================================================
// Kernel E: MHA via fp16 tensor cores. Register exp + direct half
// accumulator store. Exact l-4 pad comp. grid (48, 45, 4), block 128.
// ============================================================
__global__ __launch_bounds__(128) void mha_kernel() {
    __shared__ __align__(32) __half qh[256];
    __shared__ __align__(32) __half ph[4][256];
    __shared__ __align__(16) __half ring[4][4][2][256];

    int s = blockIdx.x, i0 = blockIdx.y * 16, h = blockIdx.z;
    int tid = threadIdx.x, lane = tid & 31, w = tid >> 5;

    for (int idx = tid; idx < 256; idx += 128) {
        int r = idx >> 4, c = idx & 15;
        int iq = min(i0 + r, NS - 1);
        float v = __half2float(g_qh[(size_t)(s * 720 + iq) * 64 + h * 16 + c]) * (0.25f * LOG2E);
        qh[idx] = __float2half(v);
    }
    __syncthreads();

    wmma::fragment<wmma::matrix_a, 16, 16, 16, __half, wmma::row_major> qa;
    wmma::load_matrix_sync(qa, qh, 16);
    wmma::fragment<wmma::matrix_b, 16, 16, 16, __half, wmma::row_major> bones;
    wmma::fill_fragment(bones, __float2half(1.0f));
    wmma::fragment<wmma::accumulator, 16, 16, 16, float> ofrag, lfrag;
    wmma::fill_fragment(ofrag, 0.0f);
    wmma::fill_fragment(lfrag, 0.0f);

    const __half* kg = g_kh + (size_t)(s * 4 + h) * 720 * 16;
    const __half* vg = g_vh + (size_t)(s * 4 + h) * 720 * 16;

    #pragma unroll
    for (int st = 0; st < 3; st++) {
        int ch = w + st * 4;
        unsigned dk = (unsigned)__cvta_generic_to_shared(&ring[w][st][0][0]) + lane * 16;
        unsigned dv = (unsigned)__cvta_generic_to_shared(&ring[w][st][1][0]) + lane * 16;
        cp_async16(dk, (const char*)(kg + ch * 256) + lane * 16);
        cp_async16(dv, (const char*)(vg + ch * 256) + lane * 16);
        asm volatile("cp.async.commit_group;");
    }

    int nch = (48 - w) / 4;
    for (int i = 0; i < nch; i++) {
        asm volatile("cp.async.wait_group 2;");
        int st = i & 3;

        wmma::fragment<wmma::matrix_b, 16, 16, 16, __half, wmma::col_major> kb;
        wmma::load_matrix_sync(kb, &ring[w][st][0][0], 16);
        wmma::fragment<wmma::accumulator, 16, 16, 16, float> cfrag;
        wmma::fill_fragment(cfrag, 0.0f);
        wmma::mma_sync(cfrag, qa, kb, cfrag);

        wmma::fragment<wmma::accumulator, 16, 16, 16, __half> hacc;
        #pragma unroll
        for (int e = 0; e < cfrag.num_elements; e++)
            hacc.x[e] = __float2half(ex2f(cfrag.x[e]));
        wmma::store_matrix_sync(&ph[w][0], hacc, 16, wmma::mem_row_major);
        __syncwarp();

        wmma::fragment<wmma::matrix_a, 16, 16, 16, __half, wmma::row_major> pa;
        wmma::load_matrix_sync(pa, &ph[w][0], 16);
        wmma::fragment<wmma::matrix_b, 16, 16, 16, __half, wmma::row_major> vb;
        wmma::load_matrix_sync(vb, &ring[w][st][1][0], 16);
        wmma::mma_sync(ofrag, pa, vb, ofrag);
        wmma::mma_sync(lfrag, pa, bones, lfrag);

        int chn = w + (i + 3) * 4;
        if (chn < 45) {
            int stn = (i + 3) & 3;
            unsigned dk = (unsigned)__cvta_generic_to_shared(&ring[w][stn][0][0]) + lane * 16;
            unsigned dv = (unsigned)__cvta_generic_to_shared(&ring[w][stn][1][0]) + lane * 16;
            cp_async16(dk, (const char*)(kg + chn * 256) + lane * 16);
            cp_async16(dv, (const char*)(vg + chn * 256) + lane * 16);
        }
        asm volatile("cp.async.commit_group;");
    }
    asm volatile("cp.async.wait_group 0;");

    float* osmw = (float*)&ring[w][0][0][0];
    float* lsmw = osmw + 256;
    wmma::store_matrix_sync(osmw, ofrag, 16, wmma::mem_row_major);
    wmma::store_matrix_sync(lsmw, lfrag, 16, wmma::mem_row_major);
    __syncthreads();

    const float* fb = (const float*)&ring[0][0][0][0];
    for (int idx = tid; idx < 256; idx += 128) {
        int r = idx >> 4, c = idx & 15;
        float o = fb[idx] + fb[1024 + idx] + fb[2048 + idx] + fb[3072 + idx];
        float l = fb[256 + r * 16] + fb[1280 + r * 16] +
                  fb[2304 + r * 16] + fb[3328 + r * 16] - 4.0f;
        int i = i0 + r;
        if (i < NS)
            g_cat[(size_t)(s * NS + i) * 2 * DD + DD + h * 16 + c] = o / l;
    }
}

// ============================================================
// Kernel F: final projection, 16 rows/block, 4-way k-split, f32x2.
// ============================================================
__global__ __launch_bounds__(256) void final_kernel(const float* __restrict__ Wp,
                                                    float* __restrict__ out) {
    __shared__ float cs[16][2 * DD];
    __shared__ float pa[4][16][64];
    int s = blockIdx.x;
    int n0 = blockIdx.y * 16;
    int tid = threadIdx.x;

    #pragma unroll
    for (int half = 0; half < 2; half++) {
        int idx = half * 256 + tid;
        int r = idx >> 5, k4 = (idx & 31) * 4;
        int nn = min(n0 + r, NS - 1);
        *(float4*)&cs[r][k4] = *(const float4*)&g_cat[(size_t)(s * NS + nn) * 2 * DD + k4];
    }
    __syncthreads();

    int c = tid & 63, kg = tid >> 6;
    unsigned long long acc2[16];
    #pragma unroll
    for (int r = 0; r < 16; r++) acc2[r] = 0ull;
    for (int k0 = kg * 32; k0 < kg * 32 + 32; k0 += 2) {
        const float* w0 = (k0 < 64) ? (Wp + k0 * DD) : (g_Wc + (k0 - 64) * DD);
        unsigned long long wv = pack2(w0[c], w0[DD + c]);
        #pragma unroll
        for (int r = 0; r < 16; r++) {
            unsigned long long cv = *(const unsigned long long*)&cs[r][k0];
            acc2[r] = ffma2(cv, wv, acc2[r]);
        }
    }
    #pragma unroll
    for (int r = 0; r < 16; r++) {
        float lo, hi;
        unpack2(acc2[r], lo, hi);
        pa[kg][r][c] = lo + hi;
    }
    __syncthreads();

    if (kg == 0) {
        #pragma unroll
        for (int r = 0; r < 16; r++) {
            int n = n0 + r;
            if (n < NS)
                out[(size_t)(s * NS + n) * DD + c] =
                    pa[0][r][c] + pa[1][r][c] + pa[2][r][c] + pa[3][r][c] + g_bc[c];
        }
    }
}

// ============================================================
extern "C" void kernel_launch(void* const* d_in, const int* in_sizes, int n_in,
                              void* d_out, int out_size) {
    const float* x      = (const float*)d_in[0];
    const int*   adj    = (const int*)d_in[1];
    const int*   ind    = (const int*)d_in[2];
    const int*   outd   = (const int*)d_in[3];
    const float* in_emb = (const float*)d_in[4];
    const float* out_emb= (const float*)d_in[5];
    const float* W      = (const float*)d_in[6];
    const float* a1     = (const float*)d_in[7];
    const float* a2     = (const float*)d_in[8];
    const float* Wq     = (const float*)d_in[9];
    const float* bq     = (const float*)d_in[10];
    const float* Wk     = (const float*)d_in[11];
    const float* bk     = (const float*)d_in[12];
    const float* Wv     = (const float*)d_in[13];
    const float* bv     = (const float*)d_in[14];
    const float* Wo     = (const float*)d_in[15];
    const float* bo     = (const float*)d_in[16];
    const float* Wp     = (const float*)d_in[17];
    const float* bp     = (const float*)d_in[18];
    float* out = (float*)d_out;

    pre_kernel<<<181, 256>>>(adj, in_emb, out_emb, ind, outd, W, a1, a2,
                             Wq, Wk, Wv, Wo, bo, Wp, bp);
    proj_kernel<<<dim3(NSAMP, (NS + BROWS - 1) / BROWS), 256>>>(x, bq, bk, bv);
    gat_kernel<<<dim3(NSAMP, NTILE), 256>>>();
    mha_kernel<<<dim3(NSAMP, NTILE, 4), 128>>>();
    final_kernel<<<dim3(NSAMP, NTILE), 256>>>(Wp, out);
}